// round 16
// baseline (speedup 1.0000x reference)
#include <cuda_runtime.h>
#include <cuda_fp16.h>
#include <math_constants.h>
#include <cstdint>

#define SEQ 2048
#define HID 1024
#define NH  16
#define HD  64
#define QKV_N (3 * HID)

// ---------------------------------------------------------------------------
// Scratch (no dynamic allocation allowed) — fp16 operands
// ---------------------------------------------------------------------------
__device__ __align__(128) __half g_Af[SEQ * HID];        // hidden fp16
__device__ __align__(128) __half g_Waf[QKV_N * HID];     // w_attn^T fp16
__device__ __align__(128) __half g_Wpf[HID * HID];       // w_proj^T fp16
__device__ __align__(128) __half g_Cf[SEQ * HID];        // attn out fp16
// per-head QKV fp16, layout [NH][SEQ][64]
__device__ __align__(128) __half g_Qf[NH * SEQ * HD];
__device__ __align__(128) __half g_Kf[NH * SEQ * HD];
__device__ __align__(128) __half g_Vf[NH * SEQ * HD];

// ---------------------------------------------------------------------------
// Helpers (baseline PTX only)
// ---------------------------------------------------------------------------
__device__ __forceinline__ uint32_t smem_u32(const void* p) {
    uint32_t a;
    asm("{ .reg .u64 t; cvta.to.shared.u64 t, %1; cvt.u32.u64 %0, t; }"
        : "=r"(a) : "l"(p));
    return a;
}
__device__ __forceinline__ void cp_async16(uint32_t dst, const void* src) {
    asm volatile("cp.async.cg.shared.global [%0], [%1], 16;"
                 :: "r"(dst), "l"(src));
}
#define CP_COMMIT() asm volatile("cp.async.commit_group;" ::: "memory")
#define CP_WAIT(n)  asm volatile("cp.async.wait_group %0;" :: "n"(n) : "memory")

__device__ __forceinline__ void ldm_x4(uint32_t* r, uint32_t addr) {
    asm volatile("ldmatrix.sync.aligned.m8n8.x4.shared.b16 {%0,%1,%2,%3}, [%4];"
                 : "=r"(r[0]), "=r"(r[1]), "=r"(r[2]), "=r"(r[3]) : "r"(addr));
}
__device__ __forceinline__ void ldm_x4_t(uint32_t* r, uint32_t addr) {
    asm volatile("ldmatrix.sync.aligned.m8n8.x4.trans.shared.b16 {%0,%1,%2,%3}, [%4];"
                 : "=r"(r[0]), "=r"(r[1]), "=r"(r[2]), "=r"(r[3]) : "r"(addr));
}
__device__ __forceinline__ void mma_f16(float* d, const uint32_t* a,
                                        uint32_t b0, uint32_t b1) {
    asm volatile(
        "mma.sync.aligned.m16n8k16.row.col.f32.f16.f16.f32 "
        "{%0,%1,%2,%3}, {%4,%5,%6,%7}, {%8,%9}, {%0,%1,%2,%3};"
        : "+f"(d[0]), "+f"(d[1]), "+f"(d[2]), "+f"(d[3])
        : "r"(a[0]), "r"(a[1]), "r"(a[2]), "r"(a[3]), "r"(b0), "r"(b1));
}
__device__ __forceinline__ uint32_t pack_f16(float a, float b) {
    __half2 t = __floats2half2_rn(a, b);
    return *reinterpret_cast<uint32_t*>(&t);
}

// ---------------------------------------------------------------------------
// Conversion kernels
// ---------------------------------------------------------------------------
__global__ void cvt_f16(const float* __restrict__ x,
                        __half* __restrict__ y, int n4) {
    int i = blockIdx.x * blockDim.x + threadIdx.x;
    if (i >= n4) return;
    float4 v = reinterpret_cast<const float4*>(x)[i];
    uint2 w;
    w.x = pack_f16(v.x, v.y);
    w.y = pack_f16(v.z, v.w);
    reinterpret_cast<uint2*>(y)[i] = w;
}

// w[K][N] fp32 -> out[N][K] fp16 (transpose)
__global__ void cvt_transpose_f16(const float* __restrict__ w,
                                  __half* __restrict__ t, int K, int N) {
    __shared__ float tile[32][33];
    int n0 = blockIdx.x * 32, k0 = blockIdx.y * 32;
    int tx = threadIdx.x, ty = threadIdx.y;
#pragma unroll
    for (int j = 0; j < 4; j++)
        tile[ty + 8 * j][tx] = w[(size_t)(k0 + ty + 8 * j) * N + n0 + tx];
    __syncthreads();
#pragma unroll
    for (int j = 0; j < 4; j++)
        t[(size_t)(n0 + ty + 8 * j) * K + k0 + tx] =
            __float2half(tile[tx][ty + 8 * j]);
}

// ---------------------------------------------------------------------------
// fp16 GEMM via mma.sync m16n8k16: C[M,N] = A[M,K] @ Bt[N,K]^T + bias
// 512 threads (16 warps, 4/SMSP), warp tile 32x32, 4-stage cp.async pipeline.
// mode 0: fp32 C + bias. mode 1: QKV split fp16 per head.
// ---------------------------------------------------------------------------
#define PITCH 80
#define MAT_BYTES (128 * PITCH)        // 10240
#define STAGE_BYTES (2 * MAT_BYTES)    // 20480 (A + B)
#define NST 4

__global__ __launch_bounds__(512, 1) void gemm_mma_f16(
    int M, int N, int K, int mode,
    const __half* __restrict__ A, const __half* __restrict__ B,
    const float* __restrict__ bias, float* __restrict__ C,
    __half* __restrict__ qf, __half* __restrict__ kf, __half* __restrict__ vf)
{
    extern __shared__ char sm[];
    const uint32_t sbase = smem_u32(sm);
    const int tid = threadIdx.x;
    const int lane = tid & 31;
    const int warp = tid >> 5;      // 0..15
    const int wm = warp & 3;        // 32-row band
    const int wn = warp >> 2;       // 32-col band
    const int m0 = blockIdx.y * 128;
    const int n0 = blockIdx.x * 128;

    const __half* srcs[2] = { A + (size_t)m0 * K, B + (size_t)n0 * K };

    float acc[2][4][4];
#pragma unroll
    for (int i = 0; i < 2; i++)
#pragma unroll
        for (int j = 0; j < 4; j++)
#pragma unroll
            for (int q = 0; q < 4; q++) acc[i][j][q] = 0.0f;

    // stage: 2 mats x 128 rows x 64B (BK = 32 fp16)
    auto load_stage = [&](int s, int kc) {
#pragma unroll
        for (int i = 0; i < 2; i++) {
            int t = tid + i * 512;
            int mat = t >> 9;
            int r = (t >> 2) & 127;
            int ch = t & 3;
            cp_async16(sbase + s * STAGE_BYTES + mat * MAT_BYTES + r * PITCH + ch * 16,
                       srcs[mat] + (size_t)r * K + kc * 32 + ch * 8);
        }
    };

    const int NC = K / 32;
#pragma unroll
    for (int s = 0; s < NST - 1; s++) {
        load_stage(s, s);
        CP_COMMIT();
    }

    const int g = lane >> 3;
    const int rl = lane & 7;

    for (int c = 0; c < NC; c++) {
        CP_WAIT(NST - 2);
        __syncthreads();

        const uint32_t st = sbase + (c % NST) * STAGE_BYTES;

#pragma unroll
        for (int k16 = 0; k16 < 2; k16++) {
            const int ch = k16 * 2 + (g >> 1);
            const int roff = rl + ((g & 1) << 3);

            uint32_t af[2][4];
#pragma unroll
            for (int mf = 0; mf < 2; mf++) {
                int row = wm * 32 + mf * 16 + roff;
                ldm_x4(af[mf], st + row * PITCH + ch * 16);
            }

            uint32_t bf[4][2];
#pragma unroll
            for (int ng = 0; ng < 2; ng++) {
                int row = wn * 32 + ng * 16 + roff;
                uint32_t r4[4];
                ldm_x4(r4, st + MAT_BYTES + row * PITCH + ch * 16);
                bf[2 * ng][0] = r4[0];     bf[2 * ng][1] = r4[2];
                bf[2 * ng + 1][0] = r4[1]; bf[2 * ng + 1][1] = r4[3];
            }

#pragma unroll
            for (int mf = 0; mf < 2; mf++)
#pragma unroll
                for (int nf = 0; nf < 4; nf++)
                    mma_f16(acc[mf][nf], af[mf], bf[nf][0], bf[nf][1]);
        }

        if (c + NST - 1 < NC)
            load_stage((c + NST - 1) % NST, c + NST - 1);
        CP_COMMIT();
    }

    // Epilogue
#pragma unroll
    for (int mf = 0; mf < 2; mf++) {
        int rbase = m0 + wm * 32 + mf * 16 + (lane >> 2);
#pragma unroll
        for (int nf = 0; nf < 4; nf++) {
            int col = n0 + wn * 32 + nf * 8 + (lane & 3) * 2;
            float2 bv = *reinterpret_cast<const float2*>(&bias[col]);
            float a0 = acc[mf][nf][0] + bv.x, a1 = acc[mf][nf][1] + bv.y;
            float a2 = acc[mf][nf][2] + bv.x, a3 = acc[mf][nf][3] + bv.y;
            if (mode == 0) {
                float2 o0 = {a0, a1}, o1 = {a2, a3};
                *reinterpret_cast<float2*>(&C[(size_t)rbase * N + col]) = o0;
                *reinterpret_cast<float2*>(&C[(size_t)(rbase + 8) * N + col]) = o1;
            } else {
                int sec = col >> 10;
                int head = (col & 1023) >> 6;
                int dim = col & 63;
                __half* d = (sec == 0) ? qf : (sec == 1) ? kf : vf;
                size_t o0 = ((size_t)head * SEQ + rbase) * HD + dim;
                size_t o1 = o0 + 8 * HD;
                *reinterpret_cast<uint32_t*>(&d[o0]) = pack_f16(a0, a1);
                *reinterpret_cast<uint32_t*>(&d[o1]) = pack_f16(a2, a3);
            }
        }
    }
}

// ---------------------------------------------------------------------------
// fp16 causal flash attention.
// Grid (16, NH), one 128-query tile per CTA, heavy tiles scheduled first
// (qb = 15 - blockIdx.x). 256 threads = 8 warps x 16 rows; 2 CTAs/SM
// resident (4 warps/SMSP) for latency hiding + full SM coverage.
// Smem: KV stages (2 x 16KB) at 0..32KB, Q tile at 32KB..48KB.
// ---------------------------------------------------------------------------
__global__ __launch_bounds__(256, 2) void attn_mma_f16(
    const __half* __restrict__ Qf_, const __half* __restrict__ Kf_,
    const __half* __restrict__ Vf_, __half* __restrict__ Cf)
{
    extern __shared__ char sm[];
    const uint32_t sb = smem_u32(sm);
    const uint32_t sq = sb + 32768;
    const int h = blockIdx.y;
    const int tid = threadIdx.x;
    const int lane = tid & 31;
    const int warp = tid >> 5;
    const size_t hb = (size_t)h * SEQ * HD;
    const float scale = 0.125f;

    const __half* Kh = Kf_ + hb;
    const __half* Vh = Vf_ + hb;

    const int qb = 15 - (int)blockIdx.x;   // heavy tiles first
    const int qbase = qb * 128;

    // ---- Load Q tile (128 rows fp16) to smem, extract A-fragments ----
    for (int i = tid; i < 128 * 8; i += 256) {
        int r = i >> 3, ch = i & 7;
        cp_async16(sq + r * 128 + ((ch ^ (r & 7)) * 16),
                   Qf_ + hb + (size_t)(qbase + r) * HD + ch * 8);
    }
    CP_COMMIT(); CP_WAIT(0);
    __syncthreads();

    uint32_t qfr[4][4];
    {
        int row = warp * 16 + (lane & 15);
#pragma unroll
        for (int ks = 0; ks < 4; ks++) {
            int ch = ks * 2 + (lane >> 4);
            ldm_x4(qfr[ks], sq + row * 128 + ((ch ^ (row & 7)) * 16));
        }
    }
    __syncthreads();

    float o[8][4];
#pragma unroll
    for (int i = 0; i < 8; i++)
#pragma unroll
        for (int j = 0; j < 4; j++) o[i][j] = 0.0f;
    float m0v = -CUDART_INF_F, m1v = -CUDART_INF_F;
    float l0v = 0.0f, l1v = 0.0f;

    auto load_kv = [&](int s, int t) {
#pragma unroll
        for (int i = 0; i < 4; i++) {
            int idx = tid + i * 256;
            int mat = idx >> 9;            // 0: K, 1: V
            int r = (idx >> 3) & 63;
            int ch = idx & 7;
            const __half* src = mat ? Vh : Kh;
            cp_async16(sb + s * 16384 + mat * 8192 + r * 128 + ((ch ^ (r & 7)) * 16),
                       src + (size_t)(t * 64 + r) * HD + ch * 8);
        }
        CP_COMMIT();
    };

    load_kv(0, 0);

    const int ntiles = 2 * qb + 2;
    for (int t = 0; t < ntiles; t++) {
        if (t + 1 < ntiles) {
            load_kv((t + 1) & 1, t + 1);
            CP_WAIT(1);
        } else {
            CP_WAIT(0);
        }
        __syncthreads();

        const uint32_t st = sb + (t & 1) * 16384;
        const bool active = (t * 64 <= qbase + warp * 16 + 15);

        if (active) {
            // ---- S = Q K^T (kg pairs for ILP) ----
            float s[8][4];
#pragma unroll
            for (int i = 0; i < 8; i++)
#pragma unroll
                for (int j = 0; j < 4; j++) s[i][j] = 0.0f;

#pragma unroll
            for (int ks = 0; ks < 4; ks++) {
#pragma unroll
                for (int kp = 0; kp < 2; kp++) {
                    uint32_t r4[2][4];
#pragma unroll
                    for (int j = 0; j < 2; j++) {
                        int key = (kp * 2 + j) * 16 + (lane & 15);
                        int ch = ks * 2 + (lane >> 4);
                        ldm_x4(r4[j], st + key * 128 + ((ch ^ (key & 7)) * 16));
                    }
                    mma_f16(s[4 * kp + 0], qfr[ks], r4[0][0], r4[0][2]);
                    mma_f16(s[4 * kp + 1], qfr[ks], r4[0][1], r4[0][3]);
                    mma_f16(s[4 * kp + 2], qfr[ks], r4[1][0], r4[1][2]);
                    mma_f16(s[4 * kp + 3], qfr[ks], r4[1][1], r4[1][3]);
                }
            }

            // ---- scale + causal mask + online softmax ----
            const bool masked = (t >= 2 * qb);
            const int gr = lane >> 2;
            const int c2 = (lane & 3) * 2;
            const int gq0 = qbase + warp * 16 + gr;
            float mx0 = -CUDART_INF_F, mx1 = -CUDART_INF_F;
#pragma unroll
            for (int nf = 0; nf < 8; nf++) {
#pragma unroll
                for (int j = 0; j < 2; j++) {
                    s[nf][j]     *= scale;
                    s[nf][2 + j] *= scale;
                    if (masked) {
                        int gk = t * 64 + nf * 8 + c2 + j;
                        if (gk > gq0)     s[nf][j]     = -CUDART_INF_F;
                        if (gk > gq0 + 8) s[nf][2 + j] = -CUDART_INF_F;
                    }
                    mx0 = fmaxf(mx0, s[nf][j]);
                    mx1 = fmaxf(mx1, s[nf][2 + j]);
                }
            }
            mx0 = fmaxf(mx0, __shfl_xor_sync(0xffffffffu, mx0, 1));
            mx0 = fmaxf(mx0, __shfl_xor_sync(0xffffffffu, mx0, 2));
            mx1 = fmaxf(mx1, __shfl_xor_sync(0xffffffffu, mx1, 1));
            mx1 = fmaxf(mx1, __shfl_xor_sync(0xffffffffu, mx1, 2));

            float mn0 = fmaxf(m0v, mx0), mn1 = fmaxf(m1v, mx1);
            float sum0 = 0.0f, sum1 = 0.0f;
#pragma unroll
            for (int nf = 0; nf < 8; nf++) {
#pragma unroll
                for (int j = 0; j < 2; j++) {
                    float p0 = __expf(s[nf][j] - mn0);
                    float p1 = __expf(s[nf][2 + j] - mn1);
                    s[nf][j] = p0;
                    s[nf][2 + j] = p1;
                    sum0 += p0;
                    sum1 += p1;
                }
            }
            sum0 += __shfl_xor_sync(0xffffffffu, sum0, 1);
            sum0 += __shfl_xor_sync(0xffffffffu, sum0, 2);
            sum1 += __shfl_xor_sync(0xffffffffu, sum1, 1);
            sum1 += __shfl_xor_sync(0xffffffffu, sum1, 2);

            float corr0 = __expf(m0v - mn0), corr1 = __expf(m1v - mn1);
            l0v = l0v * corr0 + sum0;
            l1v = l1v * corr1 + sum1;
            m0v = mn0; m1v = mn1;
#pragma unroll
            for (int nf = 0; nf < 8; nf++) {
                o[nf][0] *= corr0; o[nf][1] *= corr0;
                o[nf][2] *= corr1; o[nf][3] *= corr1;
            }

            // ---- O += P V (dg pairs for ILP) ----
#pragma unroll
            for (int ks = 0; ks < 4; ks++) {
                uint32_t pa[4];
#pragma unroll
                for (int half = 0; half < 2; half++) {
                    pa[half * 2]     = pack_f16(s[2 * ks + half][0], s[2 * ks + half][1]);
                    pa[half * 2 + 1] = pack_f16(s[2 * ks + half][2], s[2 * ks + half][3]);
                }
#pragma unroll
                for (int dp = 0; dp < 2; dp++) {
                    uint32_t r4[2][4];
#pragma unroll
                    for (int j = 0; j < 2; j++) {
                        int dg = dp * 2 + j;
                        int key = ks * 16 + (lane & 15);
                        int ch = dg * 2 + (lane >> 4);
                        ldm_x4_t(r4[j], st + 8192 + key * 128 + ((ch ^ (key & 7)) * 16));
                    }
                    mma_f16(o[4 * dp + 0], pa, r4[0][0], r4[0][1]);
                    mma_f16(o[4 * dp + 1], pa, r4[0][2], r4[0][3]);
                    mma_f16(o[4 * dp + 2], pa, r4[1][0], r4[1][1]);
                    mma_f16(o[4 * dp + 3], pa, r4[1][2], r4[1][3]);
                }
            }
        }
        __syncthreads();
    }

    // ---- Finalize: O /= l, write fp16 to Cf ----
    const float inv0 = 1.0f / l0v, inv1 = 1.0f / l1v;
    const int row0 = qbase + warp * 16 + (lane >> 2);
    const int col0 = h * HD + (lane & 3) * 2;
#pragma unroll
    for (int nf = 0; nf < 8; nf++) {
        int col = col0 + nf * 8;
        *reinterpret_cast<uint32_t*>(&Cf[(size_t)row0 * HID + col]) =
            pack_f16(o[nf][0] * inv0, o[nf][1] * inv0);
        *reinterpret_cast<uint32_t*>(&Cf[(size_t)(row0 + 8) * HID + col]) =
            pack_f16(o[nf][2] * inv1, o[nf][3] * inv1);
    }
}

// ---------------------------------------------------------------------------
extern "C" void kernel_launch(void* const* d_in, const int* in_sizes, int n_in,
                              void* d_out, int out_size)
{
    const float* H  = (const float*)d_in[0];
    const float* Wa = (const float*)d_in[1];
    const float* ba = (const float*)d_in[2];
    const float* Wp = (const float*)d_in[3];
    const float* bp = (const float*)d_in[4];
    float* out = (float*)d_out;

    __half *Af, *Waf, *Wpf, *Cf, *Qf, *Kf, *Vf;
    cudaGetSymbolAddress((void**)&Af, g_Af);
    cudaGetSymbolAddress((void**)&Waf, g_Waf);
    cudaGetSymbolAddress((void**)&Wpf, g_Wpf);
    cudaGetSymbolAddress((void**)&Cf, g_Cf);
    cudaGetSymbolAddress((void**)&Qf, g_Qf);
    cudaGetSymbolAddress((void**)&Kf, g_Kf);
    cudaGetSymbolAddress((void**)&Vf, g_Vf);

    cudaFuncSetAttribute(gemm_mma_f16,
                         cudaFuncAttributeMaxDynamicSharedMemorySize, NST * STAGE_BYTES);
    cudaFuncSetAttribute(attn_mma_f16,
                         cudaFuncAttributeMaxDynamicSharedMemorySize, 49152);

    // 0) fp16 conversions
    {
        int n4 = SEQ * HID / 4;
        cvt_f16<<<(n4 + 255) / 256, 256>>>(H, Af, n4);
        dim3 bt(32, 8);
        cvt_transpose_f16<<<dim3(QKV_N / 32, HID / 32), bt>>>(Wa, Waf, HID, QKV_N);
        cvt_transpose_f16<<<dim3(HID / 32, HID / 32), bt>>>(Wp, Wpf, HID, HID);
    }

    // 1) QKV GEMM (fp16) -> per-head Q/K/V fp16
    {
        dim3 g(QKV_N / 128, SEQ / 128);
        gemm_mma_f16<<<g, 512, NST * STAGE_BYTES>>>(
            SEQ, QKV_N, HID, 1, Af, Waf, ba, nullptr, Qf, Kf, Vf);
    }

    // 2) fp16 causal attention (heavy-first, 2 CTAs/SM) -> Cf fp16
    {
        dim3 g(16, NH);
        attn_mma_f16<<<g, 256, 49152>>>(Qf, Kf, Vf, Cf);
    }

    // 3) Output projection (fp16) -> out fp32 + bias
    {
        dim3 g(HID / 128, SEQ / 128);
        gemm_mma_f16<<<g, 512, NST * STAGE_BYTES>>>(
            SEQ, HID, HID, 0, Cf, Wpf, bp, out, nullptr, nullptr, nullptr);
    }
}